// round 2
// baseline (speedup 1.0000x reference)
#include <cuda_runtime.h>
#include <math.h>

#define N_PTS   524288
#define FD      8
#define NUM     128
#define MAXIT   5
#define EPSF    1e-6f
#define THRESH2 1e-8f        /* (1e-4)^2 */

// ---- device scratch (no allocations allowed) ----
__device__ float g_centers[NUM * FD];
__device__ int   g_counts[NUM];
__device__ float g_sums[NUM * FD];
__device__ float g_cnt[NUM];
__device__ int   g_labels[N_PTS];
__device__ __align__(16) unsigned char g_lab8[N_PTS];
__device__ int   g_converged;

// ------------------------------------------------------------------
__global__ void initKernel(const float* __restrict__ centers_in) {
    int t = threadIdx.x;                    // 1024 threads, 1 block
    g_centers[t] = centers_in[t];           // NUM*FD == 1024
    if (t == 0) g_converged = 0;
}

__global__ void prepKernel() {
    int t = threadIdx.x;                    // 128 threads
    g_counts[t] = 0;
}

// ------------------------------------------------------------------
// Per-center in-radius counts (spatial gate). Exact replication of
// in_r = sqrt_rn(dx*dx + dy*dy) <= r  via  sp2 <= Y0  (Y0 precomputed).
__global__ void __launch_bounds__(256) countKernel(const float* __restrict__ data,
                                                   float Y0) {
    if (g_converged) return;
    __shared__ float2 c2[NUM];
    __shared__ int    scnt[NUM];
    int t = threadIdx.x;
    if (t < NUM) {
        c2[t] = make_float2(g_centers[t * FD], g_centers[t * FD + 1]);
        scnt[t] = 0;
    }
    __syncthreads();

    int idx  = blockIdx.x * 256 + t;
    float2 p = *(const float2*)(data + (size_t)idx * FD);
    int lane = t & 31;

    #pragma unroll 8
    for (int i = 0; i < NUM; i++) {
        float dx = p.x - c2[i].x;
        float dy = p.y - c2[i].y;
        float sp2 = __fadd_rn(__fmul_rn(dx, dx), __fmul_rn(dy, dy));
        unsigned m = __ballot_sync(0xffffffffu, sp2 <= Y0);
        if (lane == 0) atomicAdd(&scnt[i], __popc(m));
    }
    __syncthreads();
    if (t < NUM) atomicAdd(&g_counts[t], scnt[t]);
}

// ------------------------------------------------------------------
// Assignment: faithful reference fp arithmetic.
//   D = sqrt_rn( leftfold_{k=0..7} rn((x_k - c_k) + eps)^2 )
// compare D < dval in sqrt space; poison dval=0 on non-improving active.
__global__ void __launch_bounds__(256) assignKernel(const float* __restrict__ data,
                                                    float Y0) {
    if (g_converged) return;
    __shared__ float4 sc[NUM * 2];      // centers, 2x float4 per center
    int t = threadIdx.x;

    // load centers; bake the "enough" gate into coord 0 (disabled -> +1e9
    // so sp2 can never pass the radius test; D never computed when gated)
    {
        float4 v = ((const float4*)g_centers)[t];   // 256 float4 total
        if ((t & 1) == 0) {
            if (g_counts[t >> 1] <= 1) v.x += 1e9f;
        }
        sc[t] = v;
    }
    __syncthreads();

    int idx = blockIdx.x * 256 + t;
    float4 p0 = ((const float4*)data)[2 * idx];
    float4 p1 = ((const float4*)data)[2 * idx + 1];

    float dval = 1000.0f;
    int   label = -1;

    for (int i = 0; i < NUM; i++) {
        float4 c0 = sc[2 * i];
        float dx0 = p0.x - c0.x;
        float dx1 = p0.y - c0.y;
        float sp2 = __fadd_rn(__fmul_rn(dx0, dx0), __fmul_rn(dx1, dx1));
        // need = active && not-poisoned (dval==0 means poisoned; dval>0 otherwise;
        // if dval==0 the reference would leave state unchanged anyway)
        bool need = (sp2 <= Y0) && (dval > 0.0f);
        if (__any_sync(0xffffffffu, need)) {
            float4 c1 = sc[2 * i + 1];
            float t0 = __fadd_rn(dx0, EPSF);
            float t1 = __fadd_rn(dx1, EPSF);
            float t2 = __fadd_rn(p0.z - c0.z, EPSF);
            float t3 = __fadd_rn(p0.w - c0.w, EPSF);
            float t4 = __fadd_rn(p1.x - c1.x, EPSF);
            float t5 = __fadd_rn(p1.y - c1.y, EPSF);
            float t6 = __fadd_rn(p1.z - c1.z, EPSF);
            float t7 = __fadd_rn(p1.w - c1.w, EPSF);
            float s = __fmul_rn(t0, t0);
            s = __fadd_rn(s, __fmul_rn(t1, t1));
            s = __fadd_rn(s, __fmul_rn(t2, t2));
            s = __fadd_rn(s, __fmul_rn(t3, t3));
            s = __fadd_rn(s, __fmul_rn(t4, t4));
            s = __fadd_rn(s, __fmul_rn(t5, t5));
            s = __fadd_rn(s, __fmul_rn(t6, t6));
            s = __fadd_rn(s, __fmul_rn(t7, t7));
            float D = __fsqrt_rn(s);
            if (need) {
                if (D < dval) { label = i; dval = D; }
                else          { dval = 0.0f; }
            }
        }
    }

    g_labels[idx] = label;
    g_lab8[idx]   = (unsigned char)label;   // -1 -> 0xFF (never matches 0..127)
}

// ------------------------------------------------------------------
// Deterministic segment sums: per (cluster, dim), strictly ascending
// point-index fp32 accumulation (replicates XLA CPU scatter-add order).
// 128 blocks (one per cluster) x 32 threads; lanes 0..7 = dims.
__global__ void __launch_bounds__(32) segsumKernel(const float* __restrict__ data) {
    if (g_converged) return;
    int cl   = blockIdx.x;
    int lane = threadIdx.x;
    unsigned cl4 = (unsigned)cl * 0x01010101u;

    float acc = 0.0f;
    int   cnt = 0;
    const uint4* lab16 = (const uint4*)g_lab8;

    for (int g = 0; g < N_PTS / 16; g++) {
        uint4 w = lab16[g];                       // 16 packed labels (uniform)
        unsigned m0 = __vcmpeq4(w.x, cl4);
        unsigned m1 = __vcmpeq4(w.y, cl4);
        unsigned m2 = __vcmpeq4(w.z, cl4);
        unsigned m3 = __vcmpeq4(w.w, cl4);
        if (m0 | m1 | m2 | m3) {
            int base = g * 16;
            unsigned mm[4] = {m0, m1, m2, m3};
            #pragma unroll
            for (int wi = 0; wi < 4; wi++) {
                unsigned m = mm[wi];
                if (m) {
                    #pragma unroll
                    for (int b = 0; b < 4; b++) {
                        if (m & (0xffu << (8 * b))) {
                            int pt = base + wi * 4 + b;
                            if (lane < 8)
                                acc = __fadd_rn(acc, data[(size_t)pt * FD + lane]);
                        }
                    }
                    cnt += __popc(m) >> 3;
                }
            }
        }
    }
    if (lane < 8)  g_sums[cl * FD + lane] = acc;
    if (lane == 0) g_cnt[cl] = (float)cnt;
}

// ------------------------------------------------------------------
__global__ void updateKernel() {
    if (g_converged) return;
    __shared__ float red[NUM];
    int i = threadIdx.x;                 // 128 threads
    float cnt = g_cnt[i];
    float den = fmaxf(cnt, 1.0f);
    float dsq = 0.0f;
    #pragma unroll
    for (int k = 0; k < FD; k++) {
        float oldc = g_centers[i * FD + k];
        float m    = __fdiv_rn(g_sums[i * FD + k], den);
        float nc   = (cnt > 0.0f) ? m : oldc;
        float d    = nc - oldc;
        dsq = __fadd_rn(dsq, __fmul_rn(d, d));
        g_centers[i * FD + k] = nc;
    }
    red[i] = dsq;
    __syncthreads();
    #pragma unroll
    for (int s = 64; s > 0; s >>= 1) {
        if (i < s) red[i] += red[i + s];
        __syncthreads();
    }
    if (i == 0 && red[0] < THRESH2) g_converged = 1;
}

// ------------------------------------------------------------------
// Output: [ labels as float (N) | centers (NUM*FD) ], float32
__global__ void __launch_bounds__(256) outputKernel(float* __restrict__ out, int out_size) {
    int idx = blockIdx.x * 256 + threadIdx.x;
    if (idx < N_PTS && idx < out_size)
        out[idx] = (float)g_labels[idx];
    if (idx < NUM * FD && (N_PTS + idx) < out_size)
        out[N_PTS + idx] = g_centers[idx];
}

// ------------------------------------------------------------------
extern "C" void kernel_launch(void* const* d_in, const int* in_sizes, int n_in,
                              void* d_out, int out_size) {
    const float* data    = (const float*)d_in[0];
    const float* centers = (const float*)d_in[1];

    // Y0 = largest f32 y with sqrt_rn(y) <= r, r = 0.32f (fp32 of 0.005*sqrt(4096)).
    // sqrt_rn(y) <= r  <=>  exact_sqrt(y) <= m, m = r + ulp(r)/2 (tie rounds to even
    // mantissa of r). m and m*m are exact in double (25-bit and 50-bit values).
    float  r  = 0.32f;
    double m  = 0.5 * ((double)r + (double)nextafterf(r, 2.0f));
    double m2 = m * m;
    float  Y0 = (float)m2;
    if ((double)Y0 >= m2) Y0 = nextafterf(Y0, 0.0f);

    initKernel<<<1, 1024>>>(centers);
    for (int it = 0; it < MAXIT; it++) {
        prepKernel<<<1, NUM>>>();
        countKernel<<<N_PTS / 256, 256>>>(data, Y0);
        assignKernel<<<N_PTS / 256, 256>>>(data, Y0);
        segsumKernel<<<NUM, 32>>>(data);
        updateKernel<<<1, NUM>>>();
    }
    outputKernel<<<N_PTS / 256, 256>>>((float*)d_out, out_size);
}

// round 3
// speedup vs baseline: 3.8615x; 3.8615x over previous
#include <cuda_runtime.h>
#include <math.h>

#define N_PTS   524288
#define FD      8
#define NUM     128
#define MAXIT   5
#define EPSF    1e-6f
#define THRESH2 1e-8f        /* (1e-4)^2 */
#define NBLK    (N_PTS / 256)   /* 2048 */

// ---- device scratch (no allocations allowed) ----
__device__ float g_centers[NUM * FD];
__device__ int   g_counts[NUM];
__device__ float g_sums[NUM * FD];
__device__ float g_cnt[NUM];
__device__ int   g_labels[N_PTS];
__device__ int   g_converged;
// counting-sort scratch
__device__ int   g_blockhist[NBLK * NUM];   // per-block per-cluster counts
__device__ int   g_blockpre[NBLK * NUM];    // exclusive prefix over blocks
__device__ int   g_base[NUM];               // cluster base offsets
__device__ int   g_total[NUM];              // cluster totals
__device__ int   g_idx[N_PTS];              // ascending-index point list per cluster

// ------------------------------------------------------------------
__global__ void initKernel(const float* __restrict__ centers_in) {
    int t = threadIdx.x;                    // 1024 threads, 1 block
    g_centers[t] = centers_in[t];           // NUM*FD == 1024
    if (t == 0) g_converged = 0;
}

__global__ void prepKernel() {
    g_counts[threadIdx.x] = 0;              // 128 threads
}

// ------------------------------------------------------------------
// Per-center in-radius counts (spatial gate). Exact replication of
// in_r = sqrt_rn(dx*dx + dy*dy) <= r  via  sp2 <= Y0  (Y0 precomputed).
__global__ void __launch_bounds__(256) countKernel(const float* __restrict__ data,
                                                   float Y0) {
    if (g_converged) return;
    __shared__ float2 c2[NUM];
    __shared__ int    scnt[NUM];
    int t = threadIdx.x;
    if (t < NUM) {
        c2[t] = make_float2(g_centers[t * FD], g_centers[t * FD + 1]);
        scnt[t] = 0;
    }
    __syncthreads();

    int idx  = blockIdx.x * 256 + t;
    float2 p = *(const float2*)(data + (size_t)idx * FD);
    int lane = t & 31;

    #pragma unroll 8
    for (int i = 0; i < NUM; i++) {
        float dx = p.x - c2[i].x;
        float dy = p.y - c2[i].y;
        float sp2 = __fadd_rn(__fmul_rn(dx, dx), __fmul_rn(dy, dy));
        unsigned m = __ballot_sync(0xffffffffu, sp2 <= Y0);
        if (lane == 0) atomicAdd(&scnt[i], __popc(m));
    }
    __syncthreads();
    if (t < NUM) atomicAdd(&g_counts[t], scnt[t]);
}

// ------------------------------------------------------------------
// Assignment: faithful reference fp arithmetic, + per-block label histogram.
__global__ void __launch_bounds__(256) assignKernel(const float* __restrict__ data,
                                                    float Y0) {
    if (g_converged) return;
    __shared__ float4 sc[NUM * 2];
    __shared__ int    shist[NUM];
    int t = threadIdx.x;

    {   // centers with "enough" gate baked into coord 0
        float4 v = ((const float4*)g_centers)[t];
        if ((t & 1) == 0) {
            if (g_counts[t >> 1] <= 1) v.x += 1e9f;
        }
        sc[t] = v;
    }
    if (t < NUM) shist[t] = 0;
    __syncthreads();

    int idx = blockIdx.x * 256 + t;
    float4 p0 = ((const float4*)data)[2 * idx];
    float4 p1 = ((const float4*)data)[2 * idx + 1];

    float dval = 1000.0f;
    int   label = -1;

    for (int i = 0; i < NUM; i++) {
        float4 c0 = sc[2 * i];
        float dx0 = p0.x - c0.x;
        float dx1 = p0.y - c0.y;
        float sp2 = __fadd_rn(__fmul_rn(dx0, dx0), __fmul_rn(dx1, dx1));
        bool need = (sp2 <= Y0) && (dval > 0.0f);
        if (__any_sync(0xffffffffu, need)) {
            float4 c1 = sc[2 * i + 1];
            float t0 = __fadd_rn(dx0, EPSF);
            float t1 = __fadd_rn(dx1, EPSF);
            float t2 = __fadd_rn(p0.z - c0.z, EPSF);
            float t3 = __fadd_rn(p0.w - c0.w, EPSF);
            float t4 = __fadd_rn(p1.x - c1.x, EPSF);
            float t5 = __fadd_rn(p1.y - c1.y, EPSF);
            float t6 = __fadd_rn(p1.z - c1.z, EPSF);
            float t7 = __fadd_rn(p1.w - c1.w, EPSF);
            float s = __fmul_rn(t0, t0);
            s = __fadd_rn(s, __fmul_rn(t1, t1));
            s = __fadd_rn(s, __fmul_rn(t2, t2));
            s = __fadd_rn(s, __fmul_rn(t3, t3));
            s = __fadd_rn(s, __fmul_rn(t4, t4));
            s = __fadd_rn(s, __fmul_rn(t5, t5));
            s = __fadd_rn(s, __fmul_rn(t6, t6));
            s = __fadd_rn(s, __fmul_rn(t7, t7));
            float D = __fsqrt_rn(s);
            if (need) {
                if (D < dval) { label = i; dval = D; }
                else          { dval = 0.0f; }
            }
        }
    }

    g_labels[idx] = label;
    if (label >= 0) atomicAdd(&shist[label], 1);
    __syncthreads();
    if (t < NUM) g_blockhist[blockIdx.x * NUM + t] = shist[t];
}

// ------------------------------------------------------------------
// Per-cluster exclusive scan over blocks + cluster base offsets.
// 1 block, 128 threads (thread t = cluster t).
__global__ void __launch_bounds__(NUM) scanKernel() {
    if (g_converged) return;
    __shared__ int tot[NUM];
    int t = threadIdx.x;
    int run = 0;
    #pragma unroll 8
    for (int b = 0; b < NBLK; b++) {
        int v = g_blockhist[b * NUM + t];
        g_blockpre[b * NUM + t] = run;
        run += v;
    }
    tot[t] = run;
    g_total[t] = run;
    __syncthreads();
    if (t == 0) {
        int acc = 0;
        #pragma unroll 8
        for (int c = 0; c < NUM; c++) { int v = tot[c]; tot[c] = acc; acc += v; }
    }
    __syncthreads();
    g_base[t] = tot[t];
}

// ------------------------------------------------------------------
// Stable scatter: point index -> g_idx, ascending index within each cluster.
__global__ void __launch_bounds__(256) scatterKernel() {
    if (g_converged) return;
    __shared__ int whist[8][NUM];
    int t    = threadIdx.x;
    int wid  = t >> 5;
    int lane = t & 31;

    #pragma unroll
    for (int j = t; j < 8 * NUM; j += 256) ((int*)whist)[j] = 0;
    __syncthreads();

    int idx = blockIdx.x * 256 + t;
    int lab = g_labels[idx];

    unsigned mask = __match_any_sync(0xffffffffu, lab);
    int rank   = __popc(mask & ((1u << lane) - 1u));
    int leader = __ffs(mask) - 1;
    if (lab >= 0 && lane == leader) whist[wid][lab] = __popc(mask);
    __syncthreads();

    // per-cluster exclusive prefix across the 8 warps
    if (t < NUM) {
        int run = 0;
        #pragma unroll
        for (int w = 0; w < 8; w++) {
            int v = whist[w][t];
            whist[w][t] = run;
            run += v;
        }
    }
    __syncthreads();

    if (lab >= 0) {
        int pos = g_base[lab] + g_blockpre[blockIdx.x * NUM + lab]
                + whist[wid][lab] + rank;
        g_idx[pos] = idx;
    }
}

// ------------------------------------------------------------------
// Deterministic segment sums over the compact ascending index lists.
// 128 blocks x 32 threads; lanes 0..7 chain dims serially (exact order),
// groups of 32 points give MLP=32 so L2 latency is amortized.
__global__ void __launch_bounds__(32) segsumKernel(const float* __restrict__ data) {
    if (g_converged) return;
    int cl    = blockIdx.x;
    int lane  = threadIdx.x;
    int start = g_base[cl];
    int n     = g_total[cl];

    if (lane < 8) {
        float acc = 0.0f;
        const int G = 32;
        for (int j = 0; j < n; j += G) {
            float v[G];
            #pragma unroll
            for (int k = 0; k < G; k++) {
                int jj = j + k;
                v[k] = (jj < n)
                     ? __ldg(&data[(size_t)g_idx[start + jj] * FD + lane])
                     : 0.0f;
            }
            #pragma unroll
            for (int k = 0; k < G; k++) {
                if (j + k < n) acc = __fadd_rn(acc, v[k]);
            }
        }
        g_sums[cl * FD + lane] = acc;
    }
    if (lane == 0) g_cnt[cl] = (float)n;
}

// ------------------------------------------------------------------
__global__ void updateKernel() {
    if (g_converged) return;
    __shared__ float red[NUM];
    int i = threadIdx.x;                 // 128 threads
    float cnt = g_cnt[i];
    float den = fmaxf(cnt, 1.0f);
    float dsq = 0.0f;
    #pragma unroll
    for (int k = 0; k < FD; k++) {
        float oldc = g_centers[i * FD + k];
        float m    = __fdiv_rn(g_sums[i * FD + k], den);
        float nc   = (cnt > 0.0f) ? m : oldc;
        float d    = nc - oldc;
        dsq = __fadd_rn(dsq, __fmul_rn(d, d));
        g_centers[i * FD + k] = nc;
    }
    red[i] = dsq;
    __syncthreads();
    #pragma unroll
    for (int s = 64; s > 0; s >>= 1) {
        if (i < s) red[i] += red[i + s];
        __syncthreads();
    }
    if (i == 0 && red[0] < THRESH2) g_converged = 1;
}

// ------------------------------------------------------------------
// Output: [ labels as float (N) | centers (NUM*FD) ], float32
__global__ void __launch_bounds__(256) outputKernel(float* __restrict__ out, int out_size) {
    int idx = blockIdx.x * 256 + threadIdx.x;
    if (idx < N_PTS && idx < out_size)
        out[idx] = (float)g_labels[idx];
    if (idx < NUM * FD && (N_PTS + idx) < out_size)
        out[N_PTS + idx] = g_centers[idx];
}

// ------------------------------------------------------------------
extern "C" void kernel_launch(void* const* d_in, const int* in_sizes, int n_in,
                              void* d_out, int out_size) {
    const float* data    = (const float*)d_in[0];
    const float* centers = (const float*)d_in[1];

    // Y0 = largest f32 y with sqrt_rn(y) <= r, r = 0.32f.
    float  r  = 0.32f;
    double m  = 0.5 * ((double)r + (double)nextafterf(r, 2.0f));
    double m2 = m * m;
    float  Y0 = (float)m2;
    if ((double)Y0 >= m2) Y0 = nextafterf(Y0, 0.0f);

    initKernel<<<1, 1024>>>(centers);
    for (int it = 0; it < MAXIT; it++) {
        prepKernel<<<1, NUM>>>();
        countKernel<<<NBLK, 256>>>(data, Y0);
        assignKernel<<<NBLK, 256>>>(data, Y0);
        scanKernel<<<1, NUM>>>();
        scatterKernel<<<NBLK, 256>>>();
        segsumKernel<<<NUM, 32>>>(data);
        updateKernel<<<1, NUM>>>();
    }
    outputKernel<<<NBLK, 256>>>((float*)d_out, out_size);
}

// round 4
// speedup vs baseline: 19.8260x; 5.1342x over previous
#include <cuda_runtime.h>
#include <math.h>

#define N_PTS   524288
#define FD      8
#define NUM     128
#define MAXIT   5
#define EPSF    1e-6f
#define THRESH2 1e-8f        /* (1e-4)^2 */
#define NBLK    (N_PTS / 256)   /* 2048 */
#define TPB_SEG 128
#define TILE    256

// ---- device scratch (no allocations allowed) ----
__device__ float g_centers[NUM * FD];
__device__ int   g_counts[NUM];
__device__ float g_sums[NUM * FD];
__device__ int   g_labels[N_PTS];
__device__ int   g_converged;
// counting-sort scratch
__device__ int   g_blockhist[NBLK * NUM];   // per-block per-cluster counts
__device__ int   g_blockpre[NBLK * NUM];    // exclusive prefix over blocks
__device__ int   g_base[NUM];               // cluster base offsets
__device__ int   g_total[NUM];              // cluster totals
__device__ int   g_idx[N_PTS];              // ascending-index point list per cluster

// ------------------------------------------------------------------
__global__ void initKernel(const float* __restrict__ centers_in) {
    int t = threadIdx.x;                    // 1024 threads, 1 block
    g_centers[t] = centers_in[t];           // NUM*FD == 1024
    if (t == 0) g_converged = 0;
}

__global__ void prepKernel() {
    g_counts[threadIdx.x] = 0;              // 128 threads
}

// ------------------------------------------------------------------
// Per-center in-radius counts (spatial gate). Exact replication of
// in_r = sqrt_rn(dx*dx + dy*dy) <= r  via  sp2 <= Y0  (Y0 precomputed).
__global__ void __launch_bounds__(256) countKernel(const float* __restrict__ data,
                                                   float Y0) {
    if (g_converged) return;
    __shared__ float2 c2[NUM];
    __shared__ int    scnt[NUM];
    int t = threadIdx.x;
    if (t < NUM) {
        c2[t] = make_float2(g_centers[t * FD], g_centers[t * FD + 1]);
        scnt[t] = 0;
    }
    __syncthreads();

    int idx  = blockIdx.x * 256 + t;
    float2 p = *(const float2*)(data + (size_t)idx * FD);
    int lane = t & 31;

    #pragma unroll 8
    for (int i = 0; i < NUM; i++) {
        float dx = p.x - c2[i].x;
        float dy = p.y - c2[i].y;
        float sp2 = __fadd_rn(__fmul_rn(dx, dx), __fmul_rn(dy, dy));
        unsigned m = __ballot_sync(0xffffffffu, sp2 <= Y0);
        if (lane == 0) atomicAdd(&scnt[i], __popc(m));
    }
    __syncthreads();
    if (t < NUM) atomicAdd(&g_counts[t], scnt[t]);
}

// ------------------------------------------------------------------
// Assignment: faithful reference fp arithmetic, + per-block label histogram.
__global__ void __launch_bounds__(256) assignKernel(const float* __restrict__ data,
                                                    float Y0) {
    if (g_converged) return;
    __shared__ float4 sc[NUM * 2];
    __shared__ int    shist[NUM];
    int t = threadIdx.x;

    {   // centers with "enough" gate baked into coord 0
        float4 v = ((const float4*)g_centers)[t];
        if ((t & 1) == 0) {
            if (g_counts[t >> 1] <= 1) v.x += 1e9f;
        }
        sc[t] = v;
    }
    if (t < NUM) shist[t] = 0;
    __syncthreads();

    int idx = blockIdx.x * 256 + t;
    float4 p0 = ((const float4*)data)[2 * idx];
    float4 p1 = ((const float4*)data)[2 * idx + 1];

    float dval = 1000.0f;
    int   label = -1;

    for (int i = 0; i < NUM; i++) {
        float4 c0 = sc[2 * i];
        float dx0 = p0.x - c0.x;
        float dx1 = p0.y - c0.y;
        float sp2 = __fadd_rn(__fmul_rn(dx0, dx0), __fmul_rn(dx1, dx1));
        bool need = (sp2 <= Y0) && (dval > 0.0f);
        if (__any_sync(0xffffffffu, need)) {
            float4 c1 = sc[2 * i + 1];
            float t0 = __fadd_rn(dx0, EPSF);
            float t1 = __fadd_rn(dx1, EPSF);
            float t2 = __fadd_rn(p0.z - c0.z, EPSF);
            float t3 = __fadd_rn(p0.w - c0.w, EPSF);
            float t4 = __fadd_rn(p1.x - c1.x, EPSF);
            float t5 = __fadd_rn(p1.y - c1.y, EPSF);
            float t6 = __fadd_rn(p1.z - c1.z, EPSF);
            float t7 = __fadd_rn(p1.w - c1.w, EPSF);
            float s = __fmul_rn(t0, t0);
            s = __fadd_rn(s, __fmul_rn(t1, t1));
            s = __fadd_rn(s, __fmul_rn(t2, t2));
            s = __fadd_rn(s, __fmul_rn(t3, t3));
            s = __fadd_rn(s, __fmul_rn(t4, t4));
            s = __fadd_rn(s, __fmul_rn(t5, t5));
            s = __fadd_rn(s, __fmul_rn(t6, t6));
            s = __fadd_rn(s, __fmul_rn(t7, t7));
            float D = __fsqrt_rn(s);
            if (need) {
                if (D < dval) { label = i; dval = D; }
                else          { dval = 0.0f; }
            }
        }
    }

    g_labels[idx] = label;
    if (label >= 0) atomicAdd(&shist[label], 1);
    __syncthreads();
    if (t < NUM) g_blockhist[blockIdx.x * NUM + t] = shist[t];
}

// ------------------------------------------------------------------
// Per-cluster exclusive prefix over the 2048 block histograms.
// 128 blocks (cluster = blockIdx.x) x 32 lanes; warp scan of lane sums.
__global__ void __launch_bounds__(32) scanKernel() {
    if (g_converged) return;
    int cl   = blockIdx.x;
    int lane = threadIdx.x;
    const int PER = NBLK / 32;          // 64 blocks per lane

    int s = 0;
    #pragma unroll 8
    for (int j = 0; j < PER; j++)
        s += g_blockhist[(lane * PER + j) * NUM + cl];

    // inclusive warp scan
    int inc = s;
    #pragma unroll
    for (int o = 1; o < 32; o <<= 1) {
        int v = __shfl_up_sync(0xffffffffu, inc, o);
        if (lane >= o) inc += v;
    }
    int excl = inc - s;
    if (lane == 31) g_total[cl] = inc;

    int run = excl;
    #pragma unroll 8
    for (int j = 0; j < PER; j++) {
        int idx = (lane * PER + j) * NUM + cl;
        int v = g_blockhist[idx];
        g_blockpre[idx] = run;
        run += v;
    }
}

// Exclusive scan over cluster totals -> base offsets. 1 block, 128 threads.
__global__ void __launch_bounds__(NUM) baseKernel() {
    if (g_converged) return;
    __shared__ int sh[NUM];
    int t = threadIdx.x;
    int v = g_total[t];
    sh[t] = v;
    __syncthreads();
    #pragma unroll
    for (int o = 1; o < NUM; o <<= 1) {
        int x = (t >= o) ? sh[t - o] : 0;
        __syncthreads();
        sh[t] += x;
        __syncthreads();
    }
    g_base[t] = sh[t] - v;
}

// ------------------------------------------------------------------
// Stable scatter: point index -> g_idx, ascending index within each cluster.
__global__ void __launch_bounds__(256) scatterKernel() {
    if (g_converged) return;
    __shared__ int whist[8][NUM];
    int t    = threadIdx.x;
    int wid  = t >> 5;
    int lane = t & 31;

    #pragma unroll
    for (int j = t; j < 8 * NUM; j += 256) ((int*)whist)[j] = 0;
    __syncthreads();

    int idx = blockIdx.x * 256 + t;
    int lab = g_labels[idx];

    unsigned mask = __match_any_sync(0xffffffffu, lab);
    int rank   = __popc(mask & ((1u << lane) - 1u));
    int leader = __ffs(mask) - 1;
    if (lab >= 0 && lane == leader) whist[wid][lab] = __popc(mask);
    __syncthreads();

    if (t < NUM) {
        int run = 0;
        #pragma unroll
        for (int w = 0; w < 8; w++) {
            int v = whist[w][t];
            whist[w][t] = run;
            run += v;
        }
    }
    __syncthreads();

    if (lab >= 0) {
        int pos = g_base[lab] + g_blockpre[blockIdx.x * NUM + lab]
                + whist[wid][lab] + rank;
        g_idx[pos] = idx;
    }
}

// ------------------------------------------------------------------
// Exact ascending-order segment sums, tile-pipelined.
// 128 blocks (one per cluster) x 128 threads. All warps cooperatively
// gather tile g+1 (double-buffered in smem) while warp 0 lanes 0..7 run
// the bit-exact serial left-fold over tile g (4 cyc/add chain per dim).
__global__ void __launch_bounds__(TPB_SEG) segsumKernel(const float* __restrict__ data) {
    if (g_converged) return;
    __shared__ float buf[2][TILE][FD];     // 16 KB
    int cl = blockIdx.x;
    int t  = threadIdx.x;
    int start = g_base[cl];
    int n     = g_total[cl];
    int ntiles = (n + TILE - 1) / TILE;

    // tile loader: 2 points per thread
    #define LOAD_TILE(g, s)                                              \
        do {                                                             \
            _Pragma("unroll")                                            \
            for (int h = 0; h < 2; h++) {                                \
                int p = (g) * TILE + h * TPB_SEG + t;                    \
                if (p < n) {                                             \
                    int id = g_idx[start + p];                           \
                    float4 a = ((const float4*)data)[2 * id];            \
                    float4 b = ((const float4*)data)[2 * id + 1];        \
                    float* dst = buf[s][h * TPB_SEG + t];                \
                    ((float4*)dst)[0] = a;                               \
                    ((float4*)dst)[1] = b;                               \
                }                                                        \
            }                                                            \
        } while (0)

    if (ntiles > 0) LOAD_TILE(0, 0);
    __syncthreads();

    float acc = 0.0f;
    for (int g = 0; g < ntiles; g++) {
        int s = g & 1;
        if (g + 1 < ntiles) LOAD_TILE(g + 1, s ^ 1);
        int m = min(n - g * TILE, TILE);
        if (t < FD) {
            // exact flat left-fold; LDS conflict-free (banks k*8+t)
            #pragma unroll 8
            for (int k = 0; k < m; k++)
                acc = __fadd_rn(acc, buf[s][k][t]);
        }
        __syncthreads();
    }
    if (t < FD) g_sums[cl * FD + t] = acc;
    #undef LOAD_TILE
}

// ------------------------------------------------------------------
__global__ void updateKernel() {
    if (g_converged) return;
    __shared__ float red[NUM];
    int i = threadIdx.x;                 // 128 threads
    float cnt = (float)g_total[i];
    float den = fmaxf(cnt, 1.0f);
    float dsq = 0.0f;
    #pragma unroll
    for (int k = 0; k < FD; k++) {
        float oldc = g_centers[i * FD + k];
        float m    = __fdiv_rn(g_sums[i * FD + k], den);
        float nc   = (cnt > 0.0f) ? m : oldc;
        float d    = nc - oldc;
        dsq = __fadd_rn(dsq, __fmul_rn(d, d));
        g_centers[i * FD + k] = nc;
    }
    red[i] = dsq;
    __syncthreads();
    #pragma unroll
    for (int s = 64; s > 0; s >>= 1) {
        if (i < s) red[i] += red[i + s];
        __syncthreads();
    }
    if (i == 0 && red[0] < THRESH2) g_converged = 1;
}

// ------------------------------------------------------------------
// Output: [ labels as float (N) | centers (NUM*FD) ], float32
__global__ void __launch_bounds__(256) outputKernel(float* __restrict__ out, int out_size) {
    int idx = blockIdx.x * 256 + threadIdx.x;
    if (idx < N_PTS && idx < out_size)
        out[idx] = (float)g_labels[idx];
    if (idx < NUM * FD && (N_PTS + idx) < out_size)
        out[N_PTS + idx] = g_centers[idx];
}

// ------------------------------------------------------------------
extern "C" void kernel_launch(void* const* d_in, const int* in_sizes, int n_in,
                              void* d_out, int out_size) {
    const float* data    = (const float*)d_in[0];
    const float* centers = (const float*)d_in[1];

    // Y0 = largest f32 y with sqrt_rn(y) <= r, r = 0.32f.
    float  r  = 0.32f;
    double m  = 0.5 * ((double)r + (double)nextafterf(r, 2.0f));
    double m2 = m * m;
    float  Y0 = (float)m2;
    if ((double)Y0 >= m2) Y0 = nextafterf(Y0, 0.0f);

    initKernel<<<1, 1024>>>(centers);
    for (int it = 0; it < MAXIT; it++) {
        prepKernel<<<1, NUM>>>();
        countKernel<<<NBLK, 256>>>(data, Y0);
        assignKernel<<<NBLK, 256>>>(data, Y0);
        scanKernel<<<NUM, 32>>>();
        baseKernel<<<1, NUM>>>();
        scatterKernel<<<NBLK, 256>>>();
        segsumKernel<<<NUM, TPB_SEG>>>(data);
        updateKernel<<<1, NUM>>>();
    }
    outputKernel<<<NBLK, 256>>>((float*)d_out, out_size);
}

// round 5
// speedup vs baseline: 28.2710x; 1.4260x over previous
#include <cuda_runtime.h>
#include <math.h>

#define N_PTS   524288
#define FD      8
#define NUM     128
#define MAXIT   5
#define EPSF    1e-6f
#define THRESH2 1e-8f        /* (1e-4)^2 */
#define NBLK    (N_PTS / 256)   /* 2048 */
#define TPB_SEG 256
#define TILE    512

// ---- device scratch (no allocations allowed) ----
__device__ float g_centers[NUM * FD];
__device__ int   g_counts[NUM];
__device__ float g_sums[NUM * FD];
__device__ int   g_labels[N_PTS];
__device__ int   g_converged;
// counting-sort scratch
__device__ int   g_blockhist[NBLK * NUM];   // per-block per-cluster counts
__device__ int   g_blockpre[NBLK * NUM];    // exclusive prefix over blocks
__device__ int   g_base[NUM];               // cluster base offsets
__device__ int   g_total[NUM];              // cluster totals
__device__ int   g_idx[N_PTS];              // ascending-index point list per cluster

// ------------------------------------------------------------------
__global__ void initKernel(const float* __restrict__ centers_in) {
    int t = threadIdx.x;                    // 1024 threads, 1 block
    g_centers[t] = centers_in[t];           // NUM*FD == 1024
    if (t < NUM) g_counts[t] = 0;
    if (t == 0) g_converged = 0;
}

// ------------------------------------------------------------------
// Per-center in-radius counts (spatial gate). Exact replication of
// in_r = sqrt_rn(dx*dx + dy*dy) <= r  via  sp2 <= Y0  (Y0 precomputed).
__global__ void __launch_bounds__(256) countKernel(const float* __restrict__ data,
                                                   float Y0) {
    if (g_converged) return;
    __shared__ float2 c2[NUM];
    __shared__ int    scnt[NUM];
    int t = threadIdx.x;
    if (t < NUM) {
        c2[t] = make_float2(g_centers[t * FD], g_centers[t * FD + 1]);
        scnt[t] = 0;
    }
    __syncthreads();

    int idx  = blockIdx.x * 256 + t;
    float2 p = *(const float2*)(data + (size_t)idx * FD);
    int lane = t & 31;

    #pragma unroll 8
    for (int i = 0; i < NUM; i++) {
        float dx = p.x - c2[i].x;
        float dy = p.y - c2[i].y;
        float sp2 = __fadd_rn(__fmul_rn(dx, dx), __fmul_rn(dy, dy));
        unsigned m = __ballot_sync(0xffffffffu, sp2 <= Y0);
        if (lane == 0) atomicAdd(&scnt[i], __popc(m));
    }
    __syncthreads();
    if (t < NUM) atomicAdd(&g_counts[t], scnt[t]);
}

// ------------------------------------------------------------------
// Assignment: faithful reference fp arithmetic, + per-block label histogram.
// Early warp-uniform break: once every lane is poisoned (dval==0), all
// remaining centers are provable no-ops in the reference semantics.
__global__ void __launch_bounds__(256) assignKernel(const float* __restrict__ data,
                                                    float Y0) {
    if (g_converged) return;
    __shared__ float4 sc[NUM * 2];
    __shared__ int    shist[NUM];
    int t = threadIdx.x;

    {   // centers with "enough" gate baked into coord 0
        float4 v = ((const float4*)g_centers)[t];
        if ((t & 1) == 0) {
            if (g_counts[t >> 1] <= 1) v.x += 1e9f;
        }
        sc[t] = v;
    }
    if (t < NUM) shist[t] = 0;
    __syncthreads();

    int idx = blockIdx.x * 256 + t;
    float4 p0 = ((const float4*)data)[2 * idx];
    float4 p1 = ((const float4*)data)[2 * idx + 1];

    float dval = 1000.0f;
    int   label = -1;

    for (int i = 0; i < NUM; i++) {
        float4 c0 = sc[2 * i];
        float dx0 = p0.x - c0.x;
        float dx1 = p0.y - c0.y;
        float sp2 = __fadd_rn(__fmul_rn(dx0, dx0), __fmul_rn(dx1, dx1));
        bool need = (sp2 <= Y0) && (dval > 0.0f);
        if (__any_sync(0xffffffffu, need)) {
            float4 c1 = sc[2 * i + 1];
            float t0 = __fadd_rn(dx0, EPSF);
            float t1 = __fadd_rn(dx1, EPSF);
            float t2 = __fadd_rn(p0.z - c0.z, EPSF);
            float t3 = __fadd_rn(p0.w - c0.w, EPSF);
            float t4 = __fadd_rn(p1.x - c1.x, EPSF);
            float t5 = __fadd_rn(p1.y - c1.y, EPSF);
            float t6 = __fadd_rn(p1.z - c1.z, EPSF);
            float t7 = __fadd_rn(p1.w - c1.w, EPSF);
            float s = __fmul_rn(t0, t0);
            s = __fadd_rn(s, __fmul_rn(t1, t1));
            s = __fadd_rn(s, __fmul_rn(t2, t2));
            s = __fadd_rn(s, __fmul_rn(t3, t3));
            s = __fadd_rn(s, __fmul_rn(t4, t4));
            s = __fadd_rn(s, __fmul_rn(t5, t5));
            s = __fadd_rn(s, __fmul_rn(t6, t6));
            s = __fadd_rn(s, __fmul_rn(t7, t7));
            float D = __fsqrt_rn(s);
            if (need) {
                if (D < dval) { label = i; dval = D; }
                else          { dval = 0.0f; }
            }
        } else if (__all_sync(0xffffffffu, dval == 0.0f)) {
            break;   // whole warp poisoned: nothing can change for any lane
        }
    }

    g_labels[idx] = label;
    if (label >= 0) atomicAdd(&shist[label], 1);
    __syncthreads();
    if (t < NUM) g_blockhist[blockIdx.x * NUM + t] = shist[t];
}

// ------------------------------------------------------------------
// Per-cluster exclusive prefix over the 2048 block histograms.
// 128 blocks (cluster = blockIdx.x) x 32 lanes; warp scan of lane sums.
__global__ void __launch_bounds__(32) scanKernel() {
    if (g_converged) return;
    int cl   = blockIdx.x;
    int lane = threadIdx.x;
    const int PER = NBLK / 32;          // 64 blocks per lane

    int s = 0;
    #pragma unroll 8
    for (int j = 0; j < PER; j++)
        s += g_blockhist[(lane * PER + j) * NUM + cl];

    int inc = s;
    #pragma unroll
    for (int o = 1; o < 32; o <<= 1) {
        int v = __shfl_up_sync(0xffffffffu, inc, o);
        if (lane >= o) inc += v;
    }
    int excl = inc - s;
    if (lane == 31) g_total[cl] = inc;

    int run = excl;
    #pragma unroll 8
    for (int j = 0; j < PER; j++) {
        int idx = (lane * PER + j) * NUM + cl;
        int v = g_blockhist[idx];
        g_blockpre[idx] = run;
        run += v;
    }
}

// Exclusive scan over cluster totals -> base offsets. 1 block, 128 threads.
__global__ void __launch_bounds__(NUM) baseKernel() {
    if (g_converged) return;
    __shared__ int sh[NUM];
    int t = threadIdx.x;
    int v = g_total[t];
    sh[t] = v;
    __syncthreads();
    #pragma unroll
    for (int o = 1; o < NUM; o <<= 1) {
        int x = (t >= o) ? sh[t - o] : 0;
        __syncthreads();
        sh[t] += x;
        __syncthreads();
    }
    g_base[t] = sh[t] - v;
}

// ------------------------------------------------------------------
// Stable scatter: point index -> g_idx, ascending index within each cluster.
__global__ void __launch_bounds__(256) scatterKernel() {
    if (g_converged) return;
    __shared__ int whist[8][NUM];
    int t    = threadIdx.x;
    int wid  = t >> 5;
    int lane = t & 31;

    #pragma unroll
    for (int j = t; j < 8 * NUM; j += 256) ((int*)whist)[j] = 0;
    __syncthreads();

    int idx = blockIdx.x * 256 + t;
    int lab = g_labels[idx];

    unsigned mask = __match_any_sync(0xffffffffu, lab);
    int rank   = __popc(mask & ((1u << lane) - 1u));
    int leader = __ffs(mask) - 1;
    if (lab >= 0 && lane == leader) whist[wid][lab] = __popc(mask);
    __syncthreads();

    if (t < NUM) {
        int run = 0;
        #pragma unroll
        for (int w = 0; w < 8; w++) {
            int v = whist[w][t];
            whist[w][t] = run;
            run += v;
        }
    }
    __syncthreads();

    if (lab >= 0) {
        int pos = g_base[lab] + g_blockpre[blockIdx.x * NUM + lab]
                + whist[wid][lab] + rank;
        g_idx[pos] = idx;
    }
}

// ------------------------------------------------------------------
// Exact ascending-order segment sums, tile-pipelined.
// 128 blocks (one per cluster) x 256 threads, 512-point double-buffered
// tiles. All threads gather tile g+1 while lanes 0..7 of warp 0 run the
// bit-exact serial left-fold over tile g (4 cyc/add chain per dim).
__global__ void __launch_bounds__(TPB_SEG) segsumKernel(const float* __restrict__ data) {
    if (g_converged) return;
    __shared__ float buf[2][TILE][FD];     // 32 KB
    int cl = blockIdx.x;
    int t  = threadIdx.x;
    int start = g_base[cl];
    int n     = g_total[cl];
    int ntiles = (n + TILE - 1) / TILE;

    #define LOAD_TILE(g, s)                                              \
        do {                                                             \
            _Pragma("unroll")                                            \
            for (int h = 0; h < TILE / TPB_SEG; h++) {                   \
                int p = (g) * TILE + h * TPB_SEG + t;                    \
                if (p < n) {                                             \
                    int id = g_idx[start + p];                           \
                    float4 a = ((const float4*)data)[2 * id];            \
                    float4 b = ((const float4*)data)[2 * id + 1];        \
                    float* dst = buf[s][h * TPB_SEG + t];                \
                    ((float4*)dst)[0] = a;                               \
                    ((float4*)dst)[1] = b;                               \
                }                                                        \
            }                                                            \
        } while (0)

    if (ntiles > 0) LOAD_TILE(0, 0);
    __syncthreads();

    float acc = 0.0f;
    for (int g = 0; g < ntiles; g++) {
        int s = g & 1;
        if (g + 1 < ntiles) LOAD_TILE(g + 1, s ^ 1);
        int m = min(n - g * TILE, TILE);
        if (t < FD) {
            // exact flat left-fold; LDS conflict-free (banks k*8+t)
            #pragma unroll 16
            for (int k = 0; k < m; k++)
                acc = __fadd_rn(acc, buf[s][k][t]);
        }
        __syncthreads();
    }
    if (t < FD) g_sums[cl * FD + t] = acc;
    #undef LOAD_TILE
}

// ------------------------------------------------------------------
__global__ void updateKernel() {
    if (g_converged) return;
    __shared__ float red[NUM];
    int i = threadIdx.x;                 // 128 threads
    float cnt = (float)g_total[i];
    float den = fmaxf(cnt, 1.0f);
    float dsq = 0.0f;
    #pragma unroll
    for (int k = 0; k < FD; k++) {
        float oldc = g_centers[i * FD + k];
        float m    = __fdiv_rn(g_sums[i * FD + k], den);
        float nc   = (cnt > 0.0f) ? m : oldc;
        float d    = nc - oldc;
        dsq = __fadd_rn(dsq, __fmul_rn(d, d));
        g_centers[i * FD + k] = nc;
    }
    g_counts[i] = 0;                     // reset for next iteration's count pass
    red[i] = dsq;
    __syncthreads();
    #pragma unroll
    for (int s = 64; s > 0; s >>= 1) {
        if (i < s) red[i] += red[i + s];
        __syncthreads();
    }
    if (i == 0 && red[0] < THRESH2) g_converged = 1;
}

// ------------------------------------------------------------------
// Output: [ labels as float (N) | centers (NUM*FD) ], float32
__global__ void __launch_bounds__(256) outputKernel(float* __restrict__ out, int out_size) {
    int idx = blockIdx.x * 256 + threadIdx.x;
    if (idx < N_PTS && idx < out_size)
        out[idx] = (float)g_labels[idx];
    if (idx < NUM * FD && (N_PTS + idx) < out_size)
        out[N_PTS + idx] = g_centers[idx];
}

// ------------------------------------------------------------------
extern "C" void kernel_launch(void* const* d_in, const int* in_sizes, int n_in,
                              void* d_out, int out_size) {
    const float* data    = (const float*)d_in[0];
    const float* centers = (const float*)d_in[1];

    // Y0 = largest f32 y with sqrt_rn(y) <= r, r = 0.32f.
    float  r  = 0.32f;
    double m  = 0.5 * ((double)r + (double)nextafterf(r, 2.0f));
    double m2 = m * m;
    float  Y0 = (float)m2;
    if ((double)Y0 >= m2) Y0 = nextafterf(Y0, 0.0f);

    initKernel<<<1, 1024>>>(centers);
    for (int it = 0; it < MAXIT; it++) {
        countKernel<<<NBLK, 256>>>(data, Y0);
        assignKernel<<<NBLK, 256>>>(data, Y0);
        scanKernel<<<NUM, 32>>>();
        baseKernel<<<1, NUM>>>();
        scatterKernel<<<NBLK, 256>>>();
        segsumKernel<<<NUM, TPB_SEG>>>(data);
        updateKernel<<<1, NUM>>>();
    }
    outputKernel<<<NBLK, 256>>>((float*)d_out, out_size);
}

// round 6
// speedup vs baseline: 31.5214x; 1.1150x over previous
#include <cuda_runtime.h>
#include <math.h>

#define N_PTS   524288
#define FD      8
#define NUM     128
#define MAXIT   5
#define EPSF    1e-6f
#define THRESH2 1e-8f        /* (1e-4)^2 */
#define NBLK    (N_PTS / 256)   /* 2048 */
#define TPB_SEG 256
#define TILE    768             /* 2*768*8*4 = 49152 B static smem (max) */

// ---- device scratch (no allocations allowed) ----
__device__ float g_centers[NUM * FD];
__device__ int   g_counts[NUM];
__device__ float g_sums[NUM * FD];
__device__ int   g_labels[N_PTS];
__device__ int   g_converged;
// counting-sort scratch
__device__ int   g_blockhist[NBLK * NUM];   // per-block per-cluster counts
__device__ int   g_blockpre[NBLK * NUM];    // exclusive prefix over blocks
__device__ int   g_base[NUM];               // cluster base offsets
__device__ int   g_total[NUM];              // cluster totals
__device__ int   g_idx[N_PTS];              // ascending-index point list per cluster

// ------------------------------------------------------------------
__global__ void initKernel(const float* __restrict__ centers_in) {
    int t = threadIdx.x;                    // 1024 threads, 1 block
    g_centers[t] = centers_in[t];           // NUM*FD == 1024
    if (t < NUM) g_counts[t] = 0;
    if (t == 0) g_converged = 0;
}

// ------------------------------------------------------------------
// Per-center in-radius counts (spatial gate). Exact replication of
// in_r = sqrt_rn(dx*dx + dy*dy) <= r  via  sp2 <= Y0  (Y0 precomputed).
// Register-accumulated: lane ii owns centers ii, ii+32, ii+64, ii+96
// (integer sums are order-independent; center visit order is irrelevant).
__global__ void __launch_bounds__(256) countKernel(const float* __restrict__ data,
                                                   float Y0) {
    if (g_converged) return;
    __shared__ float2 c2[NUM];
    __shared__ int    scnt[NUM];
    int t = threadIdx.x;
    if (t < NUM) {
        c2[t] = make_float2(g_centers[t * FD], g_centers[t * FD + 1]);
        scnt[t] = 0;
    }
    __syncthreads();

    int idx  = blockIdx.x * 256 + t;
    float2 p = *(const float2*)(data + (size_t)idx * FD);
    int lane = t & 31;

    int cnt0 = 0, cnt1 = 0, cnt2 = 0, cnt3 = 0;
    #pragma unroll 4
    for (int ii = 0; ii < 32; ii++) {
        bool mine = (lane == ii);
        #pragma unroll
        for (int q = 0; q < 4; q++) {
            int i = q * 32 + ii;
            float dx = p.x - c2[i].x;
            float dy = p.y - c2[i].y;
            float sp2 = __fadd_rn(__fmul_rn(dx, dx), __fmul_rn(dy, dy));
            unsigned m = __ballot_sync(0xffffffffu, sp2 <= Y0);
            int pc = __popc(m);
            if (mine) {
                if (q == 0) cnt0 += pc;
                if (q == 1) cnt1 += pc;
                if (q == 2) cnt2 += pc;
                if (q == 3) cnt3 += pc;
            }
        }
    }
    atomicAdd(&scnt[lane],      cnt0);
    atomicAdd(&scnt[lane + 32], cnt1);
    atomicAdd(&scnt[lane + 64], cnt2);
    atomicAdd(&scnt[lane + 96], cnt3);
    __syncthreads();
    if (t < NUM) atomicAdd(&g_counts[t], scnt[t]);
}

// ------------------------------------------------------------------
// Assignment: faithful reference fp arithmetic, + per-block label histogram.
// Early warp-uniform break: once every lane is poisoned (dval==0), all
// remaining centers are provable no-ops in the reference semantics.
__global__ void __launch_bounds__(256) assignKernel(const float* __restrict__ data,
                                                    float Y0) {
    if (g_converged) return;
    __shared__ float4 sc[NUM * 2];
    __shared__ int    shist[NUM];
    int t = threadIdx.x;

    {   // centers with "enough" gate baked into coord 0
        float4 v = ((const float4*)g_centers)[t];
        if ((t & 1) == 0) {
            if (g_counts[t >> 1] <= 1) v.x += 1e9f;
        }
        sc[t] = v;
    }
    if (t < NUM) shist[t] = 0;
    __syncthreads();

    int idx = blockIdx.x * 256 + t;
    float4 p0 = ((const float4*)data)[2 * idx];
    float4 p1 = ((const float4*)data)[2 * idx + 1];

    float dval = 1000.0f;
    int   label = -1;

    for (int i = 0; i < NUM; i++) {
        float4 c0 = sc[2 * i];
        float dx0 = p0.x - c0.x;
        float dx1 = p0.y - c0.y;
        float sp2 = __fadd_rn(__fmul_rn(dx0, dx0), __fmul_rn(dx1, dx1));
        bool need = (sp2 <= Y0) && (dval > 0.0f);
        if (__any_sync(0xffffffffu, need)) {
            float4 c1 = sc[2 * i + 1];
            float t0 = __fadd_rn(dx0, EPSF);
            float t1 = __fadd_rn(dx1, EPSF);
            float t2 = __fadd_rn(p0.z - c0.z, EPSF);
            float t3 = __fadd_rn(p0.w - c0.w, EPSF);
            float t4 = __fadd_rn(p1.x - c1.x, EPSF);
            float t5 = __fadd_rn(p1.y - c1.y, EPSF);
            float t6 = __fadd_rn(p1.z - c1.z, EPSF);
            float t7 = __fadd_rn(p1.w - c1.w, EPSF);
            float s = __fmul_rn(t0, t0);
            s = __fadd_rn(s, __fmul_rn(t1, t1));
            s = __fadd_rn(s, __fmul_rn(t2, t2));
            s = __fadd_rn(s, __fmul_rn(t3, t3));
            s = __fadd_rn(s, __fmul_rn(t4, t4));
            s = __fadd_rn(s, __fmul_rn(t5, t5));
            s = __fadd_rn(s, __fmul_rn(t6, t6));
            s = __fadd_rn(s, __fmul_rn(t7, t7));
            float D = __fsqrt_rn(s);
            if (need) {
                if (D < dval) { label = i; dval = D; }
                else          { dval = 0.0f; }
            }
        } else if (__all_sync(0xffffffffu, dval == 0.0f)) {
            break;   // whole warp poisoned: nothing can change for any lane
        }
    }

    g_labels[idx] = label;
    if (label >= 0) atomicAdd(&shist[label], 1);
    __syncthreads();
    if (t < NUM) g_blockhist[blockIdx.x * NUM + t] = shist[t];
}

// ------------------------------------------------------------------
// Per-cluster exclusive prefix over the 2048 block histograms.
// 128 blocks (cluster = blockIdx.x) x 128 threads; each thread owns 16
// histogram entries held in registers (MLP=16), block scan combines.
__global__ void __launch_bounds__(128) scanKernel() {
    if (g_converged) return;
    __shared__ int wsum[4];
    int cl   = blockIdx.x;
    int t    = threadIdx.x;             // 0..127
    int lane = t & 31, wid = t >> 5;
    const int PER = NBLK / 128;         // 16

    int v[PER];
    int s = 0;
    #pragma unroll
    for (int j = 0; j < PER; j++) {
        v[j] = g_blockhist[(t * PER + j) * NUM + cl];
        s += v[j];
    }

    // warp inclusive scan of thread sums
    int inc = s;
    #pragma unroll
    for (int o = 1; o < 32; o <<= 1) {
        int x = __shfl_up_sync(0xffffffffu, inc, o);
        if (lane >= o) inc += x;
    }
    if (lane == 31) wsum[wid] = inc;
    __syncthreads();
    int woff = 0;
    #pragma unroll
    for (int w = 0; w < 4; w++)
        if (w < wid) woff += wsum[w];

    if (t == 127) g_total[cl] = woff + inc;

    int run = woff + (inc - s);         // exclusive prefix for this thread
    #pragma unroll
    for (int j = 0; j < PER; j++) {
        g_blockpre[(t * PER + j) * NUM + cl] = run;
        run += v[j];
    }
}

// Exclusive scan over cluster totals -> base offsets. 1 block, 128 threads.
__global__ void __launch_bounds__(NUM) baseKernel() {
    if (g_converged) return;
    __shared__ int sh[NUM];
    int t = threadIdx.x;
    int v = g_total[t];
    sh[t] = v;
    __syncthreads();
    #pragma unroll
    for (int o = 1; o < NUM; o <<= 1) {
        int x = (t >= o) ? sh[t - o] : 0;
        __syncthreads();
        sh[t] += x;
        __syncthreads();
    }
    g_base[t] = sh[t] - v;
}

// ------------------------------------------------------------------
// Stable scatter: point index -> g_idx, ascending index within each cluster.
__global__ void __launch_bounds__(256) scatterKernel() {
    if (g_converged) return;
    __shared__ int whist[8][NUM];
    int t    = threadIdx.x;
    int wid  = t >> 5;
    int lane = t & 31;

    #pragma unroll
    for (int j = t; j < 8 * NUM; j += 256) ((int*)whist)[j] = 0;
    __syncthreads();

    int idx = blockIdx.x * 256 + t;
    int lab = g_labels[idx];

    unsigned mask = __match_any_sync(0xffffffffu, lab);
    int rank   = __popc(mask & ((1u << lane) - 1u));
    int leader = __ffs(mask) - 1;
    if (lab >= 0 && lane == leader) whist[wid][lab] = __popc(mask);
    __syncthreads();

    if (t < NUM) {
        int run = 0;
        #pragma unroll
        for (int w = 0; w < 8; w++) {
            int v = whist[w][t];
            whist[w][t] = run;
            run += v;
        }
    }
    __syncthreads();

    if (lab >= 0) {
        int pos = g_base[lab] + g_blockpre[blockIdx.x * NUM + lab]
                + whist[wid][lab] + rank;
        g_idx[pos] = idx;
    }
}

// ------------------------------------------------------------------
// Exact ascending-order segment sums, tile-pipelined.
// 128 blocks (one per cluster) x 256 threads, 768-point double-buffered
// tiles (48KB smem). All threads gather tile g+1 while lanes 0..7 of
// warp 0 run the bit-exact serial left-fold over tile g (4 cyc/add chain).
__global__ void __launch_bounds__(TPB_SEG) segsumKernel(const float* __restrict__ data) {
    if (g_converged) return;
    __shared__ float buf[2][TILE][FD];     // 49152 B
    int cl = blockIdx.x;
    int t  = threadIdx.x;
    int start = g_base[cl];
    int n     = g_total[cl];
    int ntiles = (n + TILE - 1) / TILE;

    #define LOAD_TILE(g, s)                                              \
        do {                                                             \
            _Pragma("unroll")                                            \
            for (int h = 0; h < TILE / TPB_SEG; h++) {                   \
                int p = (g) * TILE + h * TPB_SEG + t;                    \
                if (p < n) {                                             \
                    int id = g_idx[start + p];                           \
                    float4 a = ((const float4*)data)[2 * id];            \
                    float4 b = ((const float4*)data)[2 * id + 1];        \
                    float* dst = buf[s][h * TPB_SEG + t];                \
                    ((float4*)dst)[0] = a;                               \
                    ((float4*)dst)[1] = b;                               \
                }                                                        \
            }                                                            \
        } while (0)

    if (ntiles > 0) LOAD_TILE(0, 0);
    __syncthreads();

    float acc = 0.0f;
    for (int g = 0; g < ntiles; g++) {
        int s = g & 1;
        if (g + 1 < ntiles) LOAD_TILE(g + 1, s ^ 1);
        int m = min(n - g * TILE, TILE);
        if (t < FD) {
            // exact flat left-fold; LDS conflict-free (banks k*8+t)
            #pragma unroll 16
            for (int k = 0; k < m; k++)
                acc = __fadd_rn(acc, buf[s][k][t]);
        }
        __syncthreads();
    }
    if (t < FD) g_sums[cl * FD + t] = acc;
    #undef LOAD_TILE
}

// ------------------------------------------------------------------
__global__ void updateKernel() {
    if (g_converged) return;
    __shared__ float red[NUM];
    int i = threadIdx.x;                 // 128 threads
    float cnt = (float)g_total[i];
    float den = fmaxf(cnt, 1.0f);
    float dsq = 0.0f;
    #pragma unroll
    for (int k = 0; k < FD; k++) {
        float oldc = g_centers[i * FD + k];
        float m    = __fdiv_rn(g_sums[i * FD + k], den);
        float nc   = (cnt > 0.0f) ? m : oldc;
        float d    = nc - oldc;
        dsq = __fadd_rn(dsq, __fmul_rn(d, d));
        g_centers[i * FD + k] = nc;
    }
    g_counts[i] = 0;                     // reset for next iteration's count pass
    red[i] = dsq;
    __syncthreads();
    #pragma unroll
    for (int s = 64; s > 0; s >>= 1) {
        if (i < s) red[i] += red[i + s];
        __syncthreads();
    }
    if (i == 0 && red[0] < THRESH2) g_converged = 1;
}

// ------------------------------------------------------------------
// Output: [ labels as float (N) | centers (NUM*FD) ], float32
__global__ void __launch_bounds__(256) outputKernel(float* __restrict__ out, int out_size) {
    int idx = blockIdx.x * 256 + threadIdx.x;
    if (idx < N_PTS && idx < out_size)
        out[idx] = (float)g_labels[idx];
    if (idx < NUM * FD && (N_PTS + idx) < out_size)
        out[N_PTS + idx] = g_centers[idx];
}

// ------------------------------------------------------------------
extern "C" void kernel_launch(void* const* d_in, const int* in_sizes, int n_in,
                              void* d_out, int out_size) {
    const float* data    = (const float*)d_in[0];
    const float* centers = (const float*)d_in[1];

    // Y0 = largest f32 y with sqrt_rn(y) <= r, r = 0.32f.
    float  r  = 0.32f;
    double m  = 0.5 * ((double)r + (double)nextafterf(r, 2.0f));
    double m2 = m * m;
    float  Y0 = (float)m2;
    if ((double)Y0 >= m2) Y0 = nextafterf(Y0, 0.0f);

    initKernel<<<1, 1024>>>(centers);
    for (int it = 0; it < MAXIT; it++) {
        countKernel<<<NBLK, 256>>>(data, Y0);
        assignKernel<<<NBLK, 256>>>(data, Y0);
        scanKernel<<<NUM, 128>>>();
        baseKernel<<<1, NUM>>>();
        scatterKernel<<<NBLK, 256>>>();
        segsumKernel<<<NUM, TPB_SEG>>>(data);
        updateKernel<<<1, NUM>>>();
    }
    outputKernel<<<NBLK, 256>>>((float*)d_out, out_size);
}